// round 12
// baseline (speedup 1.0000x reference)
#include <cuda_runtime.h>
#include <cuda_fp16.h>
#include <math.h>
#include <stdint.h>

#define B_AG 32768
#define DID  512
#define HID  1024
#define NOPT 8
#define NACT 16

#define MT    64           // agents per CTA
#define NTILE 128          // hidden cols per tile
#define KCH   32           // K per chunk (halves)
#define NCH   (DID/KCH)    // 16
#define NT    128

// ---- smem byte layout (identical to R7) ----
#define A_HI 0
#define A_LO 5120
#define B_HI 10240
#define B_LO 20480
#define STAGE_BYTES 30720
#define ST_OFF(s)  (1024 + (s)*STAGE_BYTES)
#define HST_OFFB 1024
#define HSTS 133
#define FIN_OFFB 35072
#define FINS 20
#define HWS  20
#define HW_OFFB   62464
#define BIAS_OFFB 72704
#define MISC_OFFB 73216
#define SMEM_BYTES 73984    // x3 CTAs/SM

__device__ int    g_opt_cnt[NOPT];
__device__ int    g_opt_list[NOPT*B_AG];
__device__ int    g_meta_act[B_AG];
__device__ int    g_term_flag[B_AG];
__device__ __half g_obsHi[(size_t)B_AG*DID];
__device__ __half g_obsLo[(size_t)B_AG*DID];
__device__ __half g_wHiT[(size_t)10*HID*DID];   // K-major: [mat][h][k]
__device__ __half g_wLoT[(size_t)10*HID*DID];

// ---------------------------------------------------------------------------
__device__ __forceinline__ void cp16(uint32_t dst, const void* src) {
    asm volatile("cp.async.cg.shared.global [%0], [%1], 16;" :: "r"(dst), "l"(src));
}
#define CP_COMMIT() asm volatile("cp.async.commit_group;")

__device__ __forceinline__ void ldm4(uint32_t a, uint32_t r[4]) {
    asm volatile("ldmatrix.sync.aligned.m8n8.x4.shared.b16 {%0,%1,%2,%3}, [%4];"
        : "=r"(r[0]), "=r"(r[1]), "=r"(r[2]), "=r"(r[3]) : "r"(a));
}
__device__ __forceinline__ void mma16816(float d[4], const uint32_t a[4],
                                         uint32_t b0, uint32_t b1) {
    asm volatile("mma.sync.aligned.m16n8k16.row.col.f32.f16.f16.f32 "
        "{%0,%1,%2,%3}, {%4,%5,%6,%7}, {%8,%9}, {%0,%1,%2,%3};"
        : "+f"(d[0]), "+f"(d[1]), "+f"(d[2]), "+f"(d[3])
        : "r"(a[0]), "r"(a[1]), "r"(a[2]), "r"(a[3]), "r"(b0), "r"(b1));
}

// ---------------------------------------------------------------------------
__global__ void __launch_bounds__(256)
convert_obs_kernel(const float* __restrict__ obs) {
    size_t i = ((size_t)blockIdx.x*256 + threadIdx.x)*8;
    float v[8]; __half hi[8], lo[8];
    #pragma unroll
    for (int k = 0; k < 8; ++k) v[k] = obs[i + k];
    #pragma unroll
    for (int k = 0; k < 8; ++k) {
        hi[k] = __float2half_rn(v[k]);
        lo[k] = __float2half_rn(v[k] - __half2float(hi[k]));
    }
    *(uint4*)&g_obsHi[i] = *(uint4*)hi;
    *(uint4*)&g_obsLo[i] = *(uint4*)lo;
    if (blockIdx.x == 0 && threadIdx.x < NOPT) g_opt_cnt[threadIdx.x] = 0;
}

__global__ void __launch_bounds__(256)
convert_w_kernel(const float* __restrict__ Wm1,
                 const float* __restrict__ Wt1,
                 const float* __restrict__ W1) {
    __shared__ float tile[32][33];
    const int m = blockIdx.z;
    const float* src = (m == 0) ? Wm1 : (m == 1) ? Wt1 : W1 + (size_t)(m-2)*DID*HID;
    const int h0 = blockIdx.x * 32;
    const int k0 = blockIdx.y * 32;
    const int tx = threadIdx.x, ty0 = threadIdx.y;
    #pragma unroll
    for (int r = 0; r < 32; r += 8)
        tile[r + ty0][tx] = src[(size_t)(k0 + r + ty0)*HID + h0 + tx];
    __syncthreads();
    __half* dHi = g_wHiT + (size_t)m*HID*DID;
    __half* dLo = g_wLoT + (size_t)m*HID*DID;
    #pragma unroll
    for (int r = 0; r < 32; r += 8) {
        float x = tile[tx][r + ty0];
        __half hi = __float2half_rn(x);
        __half lo = __float2half_rn(x - __half2float(hi));
        size_t o = (size_t)(h0 + r + ty0)*DID + k0 + tx;
        dHi[o] = hi; dLo[o] = lo;
    }
}

// ---------------------------------------------------------------------------
// Core GEMM tile: [64 x 128] over K=512 (identical to R7)
// ---------------------------------------------------------------------------
__device__ __forceinline__ void gemm_tile(uint32_t su, int t,
    const __half* aHi0, const __half* aHi1,
    const __half* aLo0, const __half* aLo1,
    const __half* bHi,  const __half* bLo,
    float acc[2][8][4])
{
    const int lane = t & 31, w = t >> 5;
    const int wm = (w & 1) * 32, wn = (w >> 1) * 64;
    const uint32_t drow = (uint32_t)((t >> 2)*80 + (t & 3)*16);

    #define FILL(s, kc) do {                                    \
        uint32_t _b = su + ST_OFF(s) + drow;                    \
        const int _ko = (kc)*KCH;                               \
        cp16(_b + A_HI,        aHi0 + _ko);                     \
        cp16(_b + A_HI + 2560, aHi1 + _ko);                     \
        cp16(_b + A_LO,        aLo0 + _ko);                     \
        cp16(_b + A_LO + 2560, aLo1 + _ko);                     \
        _Pragma("unroll")                                       \
        for (int _i = 0; _i < 4; ++_i) {                        \
            cp16(_b + B_HI + _i*2560, bHi + _i*32*DID + _ko);   \
            cp16(_b + B_LO + _i*2560, bLo + _i*32*DID + _ko);   \
        }                                                       \
        CP_COMMIT();                                            \
    } while (0)

    FILL(0, 0);

    #pragma unroll 1
    for (int kc = 0; kc < NCH; ++kc) {
        const int cur = kc & 1;
        if (kc + 1 < NCH) {
            FILL(cur ^ 1, kc + 1);
            asm volatile("cp.async.wait_group 1;");
        } else {
            asm volatile("cp.async.wait_group 0;");
        }
        __syncthreads();

        const uint32_t sb = su + ST_OFF(cur);
        #pragma unroll
        for (int ks = 0; ks < 2; ++ks) {
            const uint32_t ko = ks*32 + (lane >> 4)*16;
            const uint32_t aadr = sb + A_HI + (uint32_t)((wm + (lane & 15))*80) + ko;
            uint32_t ah0[4], ah1[4], al0[4], al1[4];
            ldm4(aadr,          ah0);
            ldm4(aadr + 16*80,  ah1);
            ldm4(aadr + 5120,         al0);
            ldm4(aadr + 5120 + 16*80, al1);

            uint32_t bh[4][4], bl[4][4];
            #pragma unroll
            for (int j = 0; j < 4; ++j) {
                const uint32_t badr = sb + B_HI
                    + (uint32_t)((wn + j*16 + (lane & 15))*80) + ko;
                ldm4(badr,         bh[j]);
                ldm4(badr + 10240, bl[j]);
            }

            #pragma unroll
            for (int j = 0; j < 4; ++j) {
                mma16816(acc[0][2*j  ], ah0, bh[j][0], bh[j][2]);
                mma16816(acc[0][2*j+1], ah0, bh[j][1], bh[j][3]);
                mma16816(acc[1][2*j  ], ah1, bh[j][0], bh[j][2]);
                mma16816(acc[1][2*j+1], ah1, bh[j][1], bh[j][3]);
            }
            #pragma unroll
            for (int j = 0; j < 4; ++j) {
                mma16816(acc[0][2*j  ], ah0, bl[j][0], bl[j][2]);
                mma16816(acc[0][2*j+1], ah0, bl[j][1], bl[j][3]);
                mma16816(acc[1][2*j  ], ah1, bl[j][0], bl[j][2]);
                mma16816(acc[1][2*j+1], ah1, bl[j][1], bl[j][3]);
            }
            #pragma unroll
            for (int j = 0; j < 4; ++j) {
                mma16816(acc[0][2*j  ], al0, bh[j][0], bh[j][2]);
                mma16816(acc[0][2*j+1], al0, bh[j][1], bh[j][3]);
                mma16816(acc[1][2*j  ], al1, bh[j][0], bh[j][2]);
                mma16816(acc[1][2*j+1], al1, bh[j][1], bh[j][3]);
            }
        }
        __syncthreads();
    }
    #undef FILL
}

// relu(acc + bias) -> h staging (scalar stores; HSTS odd)
__device__ __forceinline__ void stage_h(float* smf, const float acc[2][8][4],
                                        int t) {
    const int lane = t & 31, w = t >> 5;
    const int wm = (w & 1) * 32, wn = (w >> 1) * 64;
    float* hst = smf + HST_OFFB/4;
    const float* bias_s = smf + BIAS_OFFB/4;
    #pragma unroll
    for (int im = 0; im < 2; ++im) {
        #pragma unroll
        for (int j = 0; j < 8; ++j) {
            #pragma unroll
            for (int e = 0; e < 4; ++e) {
                int row = wm + im*16 + (lane >> 2) + (e >> 1)*8;
                int col = wn + j*8 + 2*(lane & 3) + (e & 1);
                float h = acc[im][j][e] + bias_s[col];
                hst[row*HSTS + col] = fmaxf(h, 0.f);
            }
        }
    }
}

// ---------------------------------------------------------------------------
// Phase A: grid (512, 2). blockIdx.y = net (0: meta, 1: termination).
// One GEMM per CTA -> uniform work items, better wave packing.
// ---------------------------------------------------------------------------
__global__ void __launch_bounds__(NT, 3)
phaseA_kernel(const int*   __restrict__ dones,
              const int*   __restrict__ exec_opt,
              const float* __restrict__ bm1,
              const float* __restrict__ Wm_pi,
              const float* __restrict__ Wm_v,
              const float* __restrict__ Wt2,
              float* __restrict__ out)
{
    extern __shared__ float smf[];
    const uint32_t su = (uint32_t)__cvta_generic_to_shared(smf);
    const int t = threadIdx.x;
    const int g0 = blockIdx.x * MT;
    const int net = blockIdx.y;

    float* hw     = smf + HW_OFFB/4;
    float* bias_s = smf + BIAS_OFFB/4;
    float* fin    = smf + FIN_OFFB/4;
    float* hst    = smf + HST_OFFB/4;

    const size_t arow = (size_t)(g0 + (t >> 2))*DID + (t & 3)*8;
    const __half* aHi0 = g_obsHi + arow;
    const __half* aHi1 = aHi0 + (size_t)32*DID;
    const __half* aLo0 = g_obsLo + arow;
    const __half* aLo1 = aLo0 + (size_t)32*DID;

    float acc9[9];
    #pragma unroll
    for (int k = 0; k < 9; ++k) acc9[k] = 0.f;

    const int r = t & 63, cbase = (t >> 6)*64;

    #pragma unroll 1
    for (int ht = 0; ht < HID/NTILE; ++ht) {
        const int hbase = ht * NTILE;
        if (net == 0) {
            const float* wp = Wm_pi + (size_t)(hbase + t)*NOPT;
            #pragma unroll
            for (int o = 0; o < NOPT; ++o) hw[t*HWS + o] = wp[o];
            hw[t*HWS + 8] = Wm_v[hbase + t];
            bias_s[t] = bm1[hbase + t];
        } else {
            const float* wp = Wt2 + (size_t)(hbase + t)*NOPT;
            #pragma unroll
            for (int o = 0; o < NOPT; ++o) hw[t*HWS + o] = wp[o];
            bias_s[t] = 0.f;
        }
        const size_t brow = ((size_t)net*HID + hbase + (t >> 2))*DID + (t & 3)*8;
        const __half* bHi = g_wHiT + brow;
        const __half* bLo = g_wLoT + brow;

        float acc[2][8][4];
        #pragma unroll
        for (int i = 0; i < 2; ++i)
            #pragma unroll
            for (int j = 0; j < 8; ++j)
                #pragma unroll
                for (int e = 0; e < 4; ++e) acc[i][j][e] = 0.f;

        gemm_tile(su, t, aHi0, aHi1, aLo0, aLo1, bHi, bLo, acc);
        stage_h(smf, acc, t);
        __syncthreads();

        if (net == 0) {
            #pragma unroll 4
            for (int c = 0; c < 64; ++c) {
                float h = hst[r*HSTS + cbase + c];
                const float* hwc = hw + (cbase + c)*HWS;
                float4 w0 = *(const float4*)(hwc);
                float4 w1 = *(const float4*)(hwc + 4);
                acc9[0] += h*w0.x; acc9[1] += h*w0.y;
                acc9[2] += h*w0.z; acc9[3] += h*w0.w;
                acc9[4] += h*w1.x; acc9[5] += h*w1.y;
                acc9[6] += h*w1.z; acc9[7] += h*w1.w;
                acc9[8] += h*hwc[8];
            }
        } else {
            #pragma unroll 4
            for (int c = 0; c < 64; ++c) {
                float h = hst[r*HSTS + cbase + c];
                const float* hwc = hw + (cbase + c)*HWS;
                float4 w0 = *(const float4*)(hwc);
                float4 w1 = *(const float4*)(hwc + 4);
                acc9[0] += h*w0.x; acc9[1] += h*w0.y;
                acc9[2] += h*w0.z; acc9[3] += h*w0.w;
                acc9[4] += h*w1.x; acc9[5] += h*w1.y;
                acc9[6] += h*w1.z; acc9[7] += h*w1.w;
            }
        }
        __syncthreads();
    }

    if (t >= 64) {
        #pragma unroll
        for (int k = 0; k < 9; ++k) fin[r*FINS + k] = acc9[k];
    }
    __syncthreads();

    if (t < MT) {
        const int g = g0 + t;
        float tot[9];
        #pragma unroll
        for (int k = 0; k < 9; ++k) tot[k] = acc9[k] + fin[t*FINS + k];
        if (net == 0) {
            float m = tot[0]; int am = 0;
            #pragma unroll
            for (int o = 1; o < 8; ++o) if (tot[o] > m) { m = tot[o]; am = o; }
            float s = 0.f;
            #pragma unroll
            for (int o = 0; o < 8; ++o) s += expf(tot[o] - m);
            out[3*B_AG + g] = (float)am;
            out[4*B_AG + g] = tot[8];
            out[5*B_AG + g] = -logf(s);
            g_meta_act[g] = am;
        } else {
            int eo = exec_opt[g];
            float tp = 1.0f/(1.0f + expf(-tot[eo]));
            out[6*B_AG + g] = tp;
            g_term_flag[g] = ((dones[g] != 0) || (tp > 0.5f)) ? 1 : 0;
        }
    }
}

// ---------------------------------------------------------------------------
// Compaction: builds per-option agent lists from phaseA staging.
// ---------------------------------------------------------------------------
__global__ void __launch_bounds__(128)
compact_kernel(const int* __restrict__ exec_opt) {
    __shared__ int s_cnt[NOPT], s_base[NOPT];
    const int t = threadIdx.x;
    const int g = blockIdx.x*128 + t;
    if (t < NOPT) s_cnt[t] = 0;
    __syncthreads();
    const int myno = g_term_flag[g] ? g_meta_act[g] : exec_opt[g];
    const int pos = atomicAdd(&s_cnt[myno], 1);
    __syncthreads();
    if (t < NOPT) s_base[t] = atomicAdd(&g_opt_cnt[t], s_cnt[t]);
    __syncthreads();
    g_opt_list[myno*B_AG + s_base[myno] + pos] = g;
}

// ---------------------------------------------------------------------------
// Phase B: identical to R7.
// ---------------------------------------------------------------------------
__global__ void __launch_bounds__(NT, 3)
phaseB_kernel(const float* __restrict__ b1,
              const float* __restrict__ Wpi,
              const float* __restrict__ Wv,
              float* __restrict__ out)
{
    const int opt   = blockIdx.y;
    const int start = blockIdx.x * MT;
    const int cnt   = g_opt_cnt[opt];
    if (start >= cnt) return;
    const int nvalid = min(MT, cnt - start);

    extern __shared__ float smf[];
    const uint32_t su = (uint32_t)__cvta_generic_to_shared(smf);
    const int t = threadIdx.x;

    float* hw     = smf + HW_OFFB/4;
    float* bias_s = smf + BIAS_OFFB/4;
    float* fin    = smf + FIN_OFFB/4;
    float* hst    = smf + HST_OFFB/4;
    int*   idx_s  = (int*)(smf + MISC_OFFB/4);

    if (t < MT) {
        int src = opt*B_AG + start + ((t < nvalid) ? t : 0);
        idx_s[t] = g_opt_list[src];
    }
    __syncthreads();

    const size_t arow0 = (size_t)idx_s[t >> 2]*DID + (t & 3)*8;
    const size_t arow1 = (size_t)idx_s[(t >> 2) + 32]*DID + (t & 3)*8;
    const __half* aHi0 = g_obsHi + arow0;
    const __half* aHi1 = g_obsHi + arow1;
    const __half* aLo0 = g_obsLo + arow0;
    const __half* aLo1 = g_obsLo + arow1;

    const float* bg   = b1  + (size_t)opt*HID;
    const float* wpig = Wpi + (size_t)opt*HID*NACT;
    const float* wvg  = Wv  + (size_t)opt*HID;

    float accB[17];
    #pragma unroll
    for (int k = 0; k < 17; ++k) accB[k] = 0.f;

    const int r = t & 63, cbase = (t >> 6)*64;

    #pragma unroll 1
    for (int ht = 0; ht < HID/NTILE; ++ht) {
        const int hbase = ht * NTILE;
        {
            const float* wp = wpig + (size_t)(hbase + t)*NACT;
            #pragma unroll
            for (int a = 0; a < NACT; ++a) hw[t*HWS + a] = wp[a];
            hw[t*HWS + 16] = wvg[hbase + t];
            bias_s[t] = bg[hbase + t];
        }
        const size_t brow = ((size_t)(2 + opt)*HID + hbase + (t >> 2))*DID + (t & 3)*8;
        const __half* bHi = g_wHiT + brow;
        const __half* bLo = g_wLoT + brow;

        float acc[2][8][4];
        #pragma unroll
        for (int i = 0; i < 2; ++i)
            #pragma unroll
            for (int j = 0; j < 8; ++j)
                #pragma unroll
                for (int e = 0; e < 4; ++e) acc[i][j][e] = 0.f;

        gemm_tile(su, t, aHi0, aHi1, aLo0, aLo1, bHi, bLo, acc);
        stage_h(smf, acc, t);
        __syncthreads();

        #pragma unroll 2
        for (int c = 0; c < 64; ++c) {
            float h = hst[r*HSTS + cbase + c];
            const float* hwc = hw + (cbase + c)*HWS;
            float4 w0 = *(const float4*)(hwc);
            float4 w1 = *(const float4*)(hwc + 4);
            float4 w2 = *(const float4*)(hwc + 8);
            float4 w3 = *(const float4*)(hwc + 12);
            accB[0]  += h*w0.x; accB[1]  += h*w0.y;
            accB[2]  += h*w0.z; accB[3]  += h*w0.w;
            accB[4]  += h*w1.x; accB[5]  += h*w1.y;
            accB[6]  += h*w1.z; accB[7]  += h*w1.w;
            accB[8]  += h*w2.x; accB[9]  += h*w2.y;
            accB[10] += h*w2.z; accB[11] += h*w2.w;
            accB[12] += h*w3.x; accB[13] += h*w3.y;
            accB[14] += h*w3.z; accB[15] += h*w3.w;
            accB[16] += h*hwc[16];
        }
        __syncthreads();
    }

    if (t >= 64) {
        #pragma unroll
        for (int k = 0; k < 17; ++k) fin[r*FINS + k] = accB[k];
    }
    __syncthreads();

    if (t < MT && t < nvalid) {
        const int g = idx_s[t];
        float lg[16];
        #pragma unroll
        for (int a = 0; a < NACT; ++a) lg[a] = accB[a] + fin[t*FINS + a];
        float val = accB[16] + fin[t*FINS + 16];
        float m = lg[0]; int am = 0;
        #pragma unroll
        for (int a = 1; a < NACT; ++a) if (lg[a] > m) { m = lg[a]; am = a; }
        float s = 0.f;
        #pragma unroll
        for (int a = 0; a < NACT; ++a) s += expf(lg[a] - m);
        float lp = -logf(s);
        out[          g] = (float)am;
        out[  B_AG +  g] = val;
        out[2*B_AG +  g] = lp;
    }
}

extern "C" void kernel_launch(void* const* d_in, const int* in_sizes, int n_in,
                              void* d_out, int out_size) {
    const float* obs      = (const float*)d_in[0];
    const int*   dones    = (const int*)  d_in[1];
    const int*   exec_opt = (const int*)  d_in[2];
    const float* Wm1      = (const float*)d_in[3];
    const float* bm1      = (const float*)d_in[4];
    const float* Wm_pi    = (const float*)d_in[5];
    const float* Wm_v     = (const float*)d_in[6];
    const float* Wt1      = (const float*)d_in[7];
    const float* Wt2      = (const float*)d_in[8];
    const float* W1       = (const float*)d_in[9];
    const float* b1       = (const float*)d_in[10];
    const float* Wpi      = (const float*)d_in[11];
    const float* Wv       = (const float*)d_in[12];
    float* out = (float*)d_out;

    cudaFuncSetAttribute(phaseA_kernel,
                         cudaFuncAttributeMaxDynamicSharedMemorySize, SMEM_BYTES);
    cudaFuncSetAttribute(phaseB_kernel,
                         cudaFuncAttributeMaxDynamicSharedMemorySize, SMEM_BYTES);

    convert_obs_kernel<<<(B_AG*DID)/(256*8), 256>>>(obs);
    dim3 gW(HID/32, DID/32, 10);
    convert_w_kernel<<<gW, dim3(32, 8)>>>(Wm1, Wt1, W1);
    dim3 gA(B_AG/MT, 2);
    phaseA_kernel<<<gA, NT, SMEM_BYTES>>>(
        dones, exec_opt, bm1, Wm_pi, Wm_v, Wt2, out);
    compact_kernel<<<B_AG/128, 128>>>(exec_opt);
    dim3 gB(B_AG/MT, NOPT);
    phaseB_kernel<<<gB, NT, SMEM_BYTES>>>(b1, Wpi, Wv, out);
}

// round 13
// speedup vs baseline: 1.3383x; 1.3383x over previous
#include <cuda_runtime.h>
#include <cuda_fp16.h>
#include <math.h>
#include <stdint.h>

#define B_AG 32768
#define DID  512
#define HID  1024
#define NOPT 8
#define NACT 16

#define MT    64           // agents per CTA
#define NTILE 128          // hidden cols per tile
#define KCH   32           // K per chunk (halves)
#define NCH   (DID/KCH)    // 16
#define NT    128

// ---- smem byte layout (identical to R7) ----
#define A_HI 0
#define A_LO 5120
#define B_HI 10240
#define B_LO 20480
#define STAGE_BYTES 30720
#define ST_OFF(s)  (1024 + (s)*STAGE_BYTES)
#define HST_OFFB 1024
#define HSTS 133
#define FIN_OFFB 35072
#define FINS 20
#define HWS  20
#define HW_OFFB   62464
#define BIAS_OFFB 72704
#define MISC_OFFB 73216
#define SMEM_BYTES 73984

__device__ int    g_opt_cnt[NOPT];
__device__ int    g_opt_list[NOPT*B_AG];
__device__ __half g_obsHi[(size_t)B_AG*DID];
__device__ __half g_obsLo[(size_t)B_AG*DID];
__device__ __half g_wHiT[(size_t)10*HID*DID];   // K-major: [mat][h][k]
__device__ __half g_wLoT[(size_t)10*HID*DID];

// ---------------------------------------------------------------------------
__device__ __forceinline__ void cp16(uint32_t dst, const void* src) {
    asm volatile("cp.async.cg.shared.global [%0], [%1], 16;" :: "r"(dst), "l"(src));
}
#define CP_COMMIT() asm volatile("cp.async.commit_group;")

__device__ __forceinline__ void ldm4(uint32_t a, uint32_t r[4]) {
    asm volatile("ldmatrix.sync.aligned.m8n8.x4.shared.b16 {%0,%1,%2,%3}, [%4];"
        : "=r"(r[0]), "=r"(r[1]), "=r"(r[2]), "=r"(r[3]) : "r"(a));
}
// f32-accumulator MMA (main pass)
__device__ __forceinline__ void mma16816(float d[4], const uint32_t a[4],
                                         uint32_t b0, uint32_t b1) {
    asm volatile("mma.sync.aligned.m16n8k16.row.col.f32.f16.f16.f32 "
        "{%0,%1,%2,%3}, {%4,%5,%6,%7}, {%8,%9}, {%0,%1,%2,%3};"
        : "+f"(d[0]), "+f"(d[1]), "+f"(d[2]), "+f"(d[3])
        : "r"(a[0]), "r"(a[1]), "r"(a[2]), "r"(a[3]), "r"(b0), "r"(b1));
}
// fp16-accumulator MMA (correction passes; d = 2 regs = 4 halves)
__device__ __forceinline__ void mma16816h(uint32_t d[2], const uint32_t a[4],
                                          uint32_t b0, uint32_t b1) {
    asm volatile("mma.sync.aligned.m16n8k16.row.col.f16.f16.f16.f16 "
        "{%0,%1}, {%2,%3,%4,%5}, {%6,%7}, {%0,%1};"
        : "+r"(d[0]), "+r"(d[1])
        : "r"(a[0]), "r"(a[1]), "r"(a[2]), "r"(a[3]), "r"(b0), "r"(b1));
}

// ---------------------------------------------------------------------------
__global__ void __launch_bounds__(256)
convert_obs_kernel(const float* __restrict__ obs) {
    size_t i = ((size_t)blockIdx.x*256 + threadIdx.x)*8;
    float v[8]; __half hi[8], lo[8];
    #pragma unroll
    for (int k = 0; k < 8; ++k) v[k] = obs[i + k];
    #pragma unroll
    for (int k = 0; k < 8; ++k) {
        hi[k] = __float2half_rn(v[k]);
        lo[k] = __float2half_rn(v[k] - __half2float(hi[k]));
    }
    *(uint4*)&g_obsHi[i] = *(uint4*)hi;
    *(uint4*)&g_obsLo[i] = *(uint4*)lo;
    if (blockIdx.x == 0 && threadIdx.x < NOPT) g_opt_cnt[threadIdx.x] = 0;
}

__global__ void __launch_bounds__(256)
convert_w_kernel(const float* __restrict__ Wm1,
                 const float* __restrict__ Wt1,
                 const float* __restrict__ W1) {
    __shared__ float tile[32][33];
    const int m = blockIdx.z;
    const float* src = (m == 0) ? Wm1 : (m == 1) ? Wt1 : W1 + (size_t)(m-2)*DID*HID;
    const int h0 = blockIdx.x * 32;
    const int k0 = blockIdx.y * 32;
    const int tx = threadIdx.x, ty0 = threadIdx.y;
    #pragma unroll
    for (int r = 0; r < 32; r += 8)
        tile[r + ty0][tx] = src[(size_t)(k0 + r + ty0)*HID + h0 + tx];
    __syncthreads();
    __half* dHi = g_wHiT + (size_t)m*HID*DID;
    __half* dLo = g_wLoT + (size_t)m*HID*DID;
    #pragma unroll
    for (int r = 0; r < 32; r += 8) {
        float x = tile[tx][r + ty0];
        __half hi = __float2half_rn(x);
        __half lo = __float2half_rn(x - __half2float(hi));
        size_t o = (size_t)(h0 + r + ty0)*DID + k0 + tx;
        dHi[o] = hi; dLo[o] = lo;
    }
}

// ---------------------------------------------------------------------------
// Core GEMM tile: [64 x 128] over K=512.
// accF: f32 main (hi*hi). accH: fp16 corrections (hi*lo + lo*hi).
// ---------------------------------------------------------------------------
__device__ __forceinline__ void gemm_tile(uint32_t su, int t,
    const __half* aHi0, const __half* aHi1,
    const __half* aLo0, const __half* aLo1,
    const __half* bHi,  const __half* bLo,
    float accF[2][8][4], uint32_t accH[2][8][2])
{
    const int lane = t & 31, w = t >> 5;
    const int wm = (w & 1) * 32, wn = (w >> 1) * 64;
    const uint32_t drow = (uint32_t)((t >> 2)*80 + (t & 3)*16);

    #define FILL(s, kc) do {                                    \
        uint32_t _b = su + ST_OFF(s) + drow;                    \
        const int _ko = (kc)*KCH;                               \
        cp16(_b + A_HI,        aHi0 + _ko);                     \
        cp16(_b + A_HI + 2560, aHi1 + _ko);                     \
        cp16(_b + A_LO,        aLo0 + _ko);                     \
        cp16(_b + A_LO + 2560, aLo1 + _ko);                     \
        _Pragma("unroll")                                       \
        for (int _i = 0; _i < 4; ++_i) {                        \
            cp16(_b + B_HI + _i*2560, bHi + _i*32*DID + _ko);   \
            cp16(_b + B_LO + _i*2560, bLo + _i*32*DID + _ko);   \
        }                                                       \
        CP_COMMIT();                                            \
    } while (0)

    FILL(0, 0);

    #pragma unroll 1
    for (int kc = 0; kc < NCH; ++kc) {
        const int cur = kc & 1;
        if (kc + 1 < NCH) {
            FILL(cur ^ 1, kc + 1);
            asm volatile("cp.async.wait_group 1;");
        } else {
            asm volatile("cp.async.wait_group 0;");
        }
        __syncthreads();

        const uint32_t sb = su + ST_OFF(cur);
        #pragma unroll
        for (int ks = 0; ks < 2; ++ks) {
            const uint32_t ko = ks*32 + (lane >> 4)*16;
            const uint32_t aadr = sb + A_HI + (uint32_t)((wm + (lane & 15))*80) + ko;
            uint32_t ah0[4], ah1[4], al0[4], al1[4];
            ldm4(aadr,          ah0);
            ldm4(aadr + 16*80,  ah1);
            ldm4(aadr + 5120,         al0);
            ldm4(aadr + 5120 + 16*80, al1);

            uint32_t bh[4][4], bl[4][4];
            #pragma unroll
            for (int j = 0; j < 4; ++j) {
                const uint32_t badr = sb + B_HI
                    + (uint32_t)((wn + j*16 + (lane & 15))*80) + ko;
                ldm4(badr,         bh[j]);
                ldm4(badr + 10240, bl[j]);
            }

            // pass 1: hi*hi (f32 acc)
            #pragma unroll
            for (int j = 0; j < 4; ++j) {
                mma16816(accF[0][2*j  ], ah0, bh[j][0], bh[j][2]);
                mma16816(accF[0][2*j+1], ah0, bh[j][1], bh[j][3]);
                mma16816(accF[1][2*j  ], ah1, bh[j][0], bh[j][2]);
                mma16816(accF[1][2*j+1], ah1, bh[j][1], bh[j][3]);
            }
            // pass 2: hi*lo (fp16 acc)
            #pragma unroll
            for (int j = 0; j < 4; ++j) {
                mma16816h(accH[0][2*j  ], ah0, bl[j][0], bl[j][2]);
                mma16816h(accH[0][2*j+1], ah0, bl[j][1], bl[j][3]);
                mma16816h(accH[1][2*j  ], ah1, bl[j][0], bl[j][2]);
                mma16816h(accH[1][2*j+1], ah1, bl[j][1], bl[j][3]);
            }
            // pass 3: lo*hi (fp16 acc)
            #pragma unroll
            for (int j = 0; j < 4; ++j) {
                mma16816h(accH[0][2*j  ], al0, bh[j][0], bh[j][2]);
                mma16816h(accH[0][2*j+1], al0, bh[j][1], bh[j][3]);
                mma16816h(accH[1][2*j  ], al1, bh[j][0], bh[j][2]);
                mma16816h(accH[1][2*j+1], al1, bh[j][1], bh[j][3]);
            }
        }
        __syncthreads();
    }
    #undef FILL
}

// relu(accF + corr + bias) -> h staging (scalar stores; HSTS odd)
__device__ __forceinline__ void stage_h(float* smf, const float accF[2][8][4],
                                        const uint32_t accH[2][8][2], int t) {
    const int lane = t & 31, w = t >> 5;
    const int wm = (w & 1) * 32, wn = (w >> 1) * 64;
    float* hst = smf + HST_OFFB/4;
    const float* bias_s = smf + BIAS_OFFB/4;
    #pragma unroll
    for (int im = 0; im < 2; ++im) {
        #pragma unroll
        for (int j = 0; j < 8; ++j) {
            #pragma unroll
            for (int e = 0; e < 4; ++e) {
                int row = wm + im*16 + (lane >> 2) + (e >> 1)*8;
                int col = wn + j*8 + 2*(lane & 3) + (e & 1);
                __half2 hp = *(const __half2*)&accH[im][j][e >> 1];
                float corr = __half2float((e & 1) ? __high2half(hp)
                                                  : __low2half(hp));
                float h = accF[im][j][e] + corr + bias_s[col];
                hst[row*HSTS + col] = fmaxf(h, 0.f);
            }
        }
    }
}

#define ZERO_ACCS() do {                                         \
    _Pragma("unroll") for (int _i = 0; _i < 2; ++_i)             \
    _Pragma("unroll") for (int _j = 0; _j < 8; ++_j) {           \
        _Pragma("unroll") for (int _e = 0; _e < 4; ++_e)         \
            accF[_i][_j][_e] = 0.f;                              \
        accH[_i][_j][0] = 0u; accH[_i][_j][1] = 0u;              \
    }                                                            \
} while (0)

// ---------------------------------------------------------------------------
// Phase A: fused meta + termination nets (R7 structure).
// ---------------------------------------------------------------------------
__global__ void __launch_bounds__(NT, 2)
phaseA_kernel(const int*   __restrict__ dones,
              const int*   __restrict__ exec_opt,
              const float* __restrict__ bm1,
              const float* __restrict__ Wm_pi,
              const float* __restrict__ Wm_v,
              const float* __restrict__ Wt2,
              float* __restrict__ out)
{
    extern __shared__ float smf[];
    const uint32_t su = (uint32_t)__cvta_generic_to_shared(smf);
    const int t = threadIdx.x;
    const int g0 = blockIdx.x * MT;

    float* hw     = smf + HW_OFFB/4;
    float* bias_s = smf + BIAS_OFFB/4;
    float* fin    = smf + FIN_OFFB/4;
    float* hst    = smf + HST_OFFB/4;
    int*   icnt   = (int*)(smf + MISC_OFFB/4);

    const size_t arow = (size_t)(g0 + (t >> 2))*DID + (t & 3)*8;
    const __half* aHi0 = g_obsHi + arow;
    const __half* aHi1 = aHi0 + (size_t)32*DID;
    const __half* aLo0 = g_obsLo + arow;
    const __half* aLo1 = aLo0 + (size_t)32*DID;

    float accM[9], accT[8];
    #pragma unroll
    for (int k = 0; k < 9; ++k) accM[k] = 0.f;
    #pragma unroll
    for (int k = 0; k < 8; ++k) accT[k] = 0.f;

    const int r = t & 63, cbase = (t >> 6)*64;

    #pragma unroll 1
    for (int net = 0; net < 2; ++net) {
        #pragma unroll 1
        for (int ht = 0; ht < HID/NTILE; ++ht) {
            const int hbase = ht * NTILE;
            if (net == 0) {
                const float* wp = Wm_pi + (size_t)(hbase + t)*NOPT;
                #pragma unroll
                for (int o = 0; o < NOPT; ++o) hw[t*HWS + o] = wp[o];
                hw[t*HWS + 8] = Wm_v[hbase + t];
                bias_s[t] = bm1[hbase + t];
            } else {
                const float* wp = Wt2 + (size_t)(hbase + t)*NOPT;
                #pragma unroll
                for (int o = 0; o < NOPT; ++o) hw[t*HWS + o] = wp[o];
                bias_s[t] = 0.f;
            }
            const size_t brow = ((size_t)net*HID + hbase + (t >> 2))*DID + (t & 3)*8;
            const __half* bHi = g_wHiT + brow;
            const __half* bLo = g_wLoT + brow;

            float accF[2][8][4];
            uint32_t accH[2][8][2];
            ZERO_ACCS();

            gemm_tile(su, t, aHi0, aHi1, aLo0, aLo1, bHi, bLo, accF, accH);
            stage_h(smf, accF, accH, t);
            __syncthreads();

            if (net == 0) {
                #pragma unroll 4
                for (int c = 0; c < 64; ++c) {
                    float h = hst[r*HSTS + cbase + c];
                    const float* hwc = hw + (cbase + c)*HWS;
                    float4 w0 = *(const float4*)(hwc);
                    float4 w1 = *(const float4*)(hwc + 4);
                    accM[0] += h*w0.x; accM[1] += h*w0.y;
                    accM[2] += h*w0.z; accM[3] += h*w0.w;
                    accM[4] += h*w1.x; accM[5] += h*w1.y;
                    accM[6] += h*w1.z; accM[7] += h*w1.w;
                    accM[8] += h*hwc[8];
                }
            } else {
                #pragma unroll 4
                for (int c = 0; c < 64; ++c) {
                    float h = hst[r*HSTS + cbase + c];
                    const float* hwc = hw + (cbase + c)*HWS;
                    float4 w0 = *(const float4*)(hwc);
                    float4 w1 = *(const float4*)(hwc + 4);
                    accT[0] += h*w0.x; accT[1] += h*w0.y;
                    accT[2] += h*w0.z; accT[3] += h*w0.w;
                    accT[4] += h*w1.x; accT[5] += h*w1.y;
                    accT[6] += h*w1.z; accT[7] += h*w1.w;
                }
            }
            __syncthreads();
        }
    }

    if (t >= 64) {
        #pragma unroll
        for (int k = 0; k < 9; ++k) fin[r*FINS + k] = accM[k];
        #pragma unroll
        for (int k = 0; k < 8; ++k) fin[r*FINS + 9 + k] = accT[k];
    }
    int* s_cnt  = icnt + 160;
    int* s_base = icnt + 168;
    if (t < NOPT) s_cnt[t] = 0;
    __syncthreads();

    int myno = 0, mypos = 0;
    if (t < MT) {
        const int g = g0 + t;
        float lg[8];
        #pragma unroll
        for (int o = 0; o < 8; ++o) lg[o] = accM[o] + fin[t*FINS + o];
        float mv = accM[8] + fin[t*FINS + 8];
        float m = lg[0]; int am = 0;
        #pragma unroll
        for (int o = 1; o < 8; ++o) if (lg[o] > m) { m = lg[o]; am = o; }
        float s = 0.f;
        #pragma unroll
        for (int o = 0; o < 8; ++o) s += expf(lg[o] - m);
        float lp = -logf(s);
        int eo = exec_opt[g];
        float tl = accT[eo] + fin[t*FINS + 9 + eo];
        float tp = 1.0f/(1.0f + expf(-tl));
        bool dn = (dones[g] != 0);
        bool term = dn || (tp > 0.5f);
        myno = term ? am : eo;
        out[3*B_AG + g] = (float)am;
        out[4*B_AG + g] = mv;
        out[5*B_AG + g] = lp;
        out[6*B_AG + g] = tp;
        mypos = atomicAdd(&s_cnt[myno], 1);
    }
    __syncthreads();
    if (t < NOPT) s_base[t] = atomicAdd(&g_opt_cnt[t], s_cnt[t]);
    __syncthreads();
    if (t < MT) g_opt_list[myno*B_AG + s_base[myno] + mypos] = g0 + t;
}

// ---------------------------------------------------------------------------
// Phase B: per-option sub-policy on compacted lists (R7 structure).
// ---------------------------------------------------------------------------
__global__ void __launch_bounds__(NT, 2)
phaseB_kernel(const float* __restrict__ b1,
              const float* __restrict__ Wpi,
              const float* __restrict__ Wv,
              float* __restrict__ out)
{
    const int opt   = blockIdx.y;
    const int start = blockIdx.x * MT;
    const int cnt   = g_opt_cnt[opt];
    if (start >= cnt) return;
    const int nvalid = min(MT, cnt - start);

    extern __shared__ float smf[];
    const uint32_t su = (uint32_t)__cvta_generic_to_shared(smf);
    const int t = threadIdx.x;

    float* hw     = smf + HW_OFFB/4;
    float* bias_s = smf + BIAS_OFFB/4;
    float* fin    = smf + FIN_OFFB/4;
    float* hst    = smf + HST_OFFB/4;
    int*   idx_s  = (int*)(smf + MISC_OFFB/4);

    if (t < MT) {
        int src = opt*B_AG + start + ((t < nvalid) ? t : 0);
        idx_s[t] = g_opt_list[src];
    }
    __syncthreads();

    const size_t arow0 = (size_t)idx_s[t >> 2]*DID + (t & 3)*8;
    const size_t arow1 = (size_t)idx_s[(t >> 2) + 32]*DID + (t & 3)*8;
    const __half* aHi0 = g_obsHi + arow0;
    const __half* aHi1 = g_obsHi + arow1;
    const __half* aLo0 = g_obsLo + arow0;
    const __half* aLo1 = g_obsLo + arow1;

    const float* bg   = b1  + (size_t)opt*HID;
    const float* wpig = Wpi + (size_t)opt*HID*NACT;
    const float* wvg  = Wv  + (size_t)opt*HID;

    float accB[17];
    #pragma unroll
    for (int k = 0; k < 17; ++k) accB[k] = 0.f;

    const int r = t & 63, cbase = (t >> 6)*64;

    #pragma unroll 1
    for (int ht = 0; ht < HID/NTILE; ++ht) {
        const int hbase = ht * NTILE;
        {
            const float* wp = wpig + (size_t)(hbase + t)*NACT;
            #pragma unroll
            for (int a = 0; a < NACT; ++a) hw[t*HWS + a] = wp[a];
            hw[t*HWS + 16] = wvg[hbase + t];
            bias_s[t] = bg[hbase + t];
        }
        const size_t brow = ((size_t)(2 + opt)*HID + hbase + (t >> 2))*DID + (t & 3)*8;
        const __half* bHi = g_wHiT + brow;
        const __half* bLo = g_wLoT + brow;

        float accF[2][8][4];
        uint32_t accH[2][8][2];
        ZERO_ACCS();

        gemm_tile(su, t, aHi0, aHi1, aLo0, aLo1, bHi, bLo, accF, accH);
        stage_h(smf, accF, accH, t);
        __syncthreads();

        #pragma unroll 2
        for (int c = 0; c < 64; ++c) {
            float h = hst[r*HSTS + cbase + c];
            const float* hwc = hw + (cbase + c)*HWS;
            float4 w0 = *(const float4*)(hwc);
            float4 w1 = *(const float4*)(hwc + 4);
            float4 w2 = *(const float4*)(hwc + 8);
            float4 w3 = *(const float4*)(hwc + 12);
            accB[0]  += h*w0.x; accB[1]  += h*w0.y;
            accB[2]  += h*w0.z; accB[3]  += h*w0.w;
            accB[4]  += h*w1.x; accB[5]  += h*w1.y;
            accB[6]  += h*w1.z; accB[7]  += h*w1.w;
            accB[8]  += h*w2.x; accB[9]  += h*w2.y;
            accB[10] += h*w2.z; accB[11] += h*w2.w;
            accB[12] += h*w3.x; accB[13] += h*w3.y;
            accB[14] += h*w3.z; accB[15] += h*w3.w;
            accB[16] += h*hwc[16];
        }
        __syncthreads();
    }

    if (t >= 64) {
        #pragma unroll
        for (int k = 0; k < 17; ++k) fin[r*FINS + k] = accB[k];
    }
    __syncthreads();

    if (t < MT && t < nvalid) {
        const int g = idx_s[t];
        float lg[16];
        #pragma unroll
        for (int a = 0; a < NACT; ++a) lg[a] = accB[a] + fin[t*FINS + a];
        float val = accB[16] + fin[t*FINS + 16];
        float m = lg[0]; int am = 0;
        #pragma unroll
        for (int a = 1; a < NACT; ++a) if (lg[a] > m) { m = lg[a]; am = a; }
        float s = 0.f;
        #pragma unroll
        for (int a = 0; a < NACT; ++a) s += expf(lg[a] - m);
        float lp = -logf(s);
        out[          g] = (float)am;
        out[  B_AG +  g] = val;
        out[2*B_AG +  g] = lp;
    }
}

extern "C" void kernel_launch(void* const* d_in, const int* in_sizes, int n_in,
                              void* d_out, int out_size) {
    const float* obs      = (const float*)d_in[0];
    const int*   dones    = (const int*)  d_in[1];
    const int*   exec_opt = (const int*)  d_in[2];
    const float* Wm1      = (const float*)d_in[3];
    const float* bm1      = (const float*)d_in[4];
    const float* Wm_pi    = (const float*)d_in[5];
    const float* Wm_v     = (const float*)d_in[6];
    const float* Wt1      = (const float*)d_in[7];
    const float* Wt2      = (const float*)d_in[8];
    const float* W1       = (const float*)d_in[9];
    const float* b1       = (const float*)d_in[10];
    const float* Wpi      = (const float*)d_in[11];
    const float* Wv       = (const float*)d_in[12];
    float* out = (float*)d_out;

    cudaFuncSetAttribute(phaseA_kernel,
                         cudaFuncAttributeMaxDynamicSharedMemorySize, SMEM_BYTES);
    cudaFuncSetAttribute(phaseB_kernel,
                         cudaFuncAttributeMaxDynamicSharedMemorySize, SMEM_BYTES);

    convert_obs_kernel<<<(B_AG*DID)/(256*8), 256>>>(obs);
    dim3 gW(HID/32, DID/32, 10);
    convert_w_kernel<<<gW, dim3(32, 8)>>>(Wm1, Wt1, W1);
    phaseA_kernel<<<B_AG/MT, NT, SMEM_BYTES>>>(
        dones, exec_opt, bm1, Wm_pi, Wm_v, Wt2, out);
    dim3 gB(B_AG/MT, NOPT);
    phaseB_kernel<<<gB, NT, SMEM_BYTES>>>(b1, Wpi, Wv, out);
}